// round 1
// baseline (speedup 1.0000x reference)
#include <cuda_runtime.h>
#include <math.h>

// ---------------- constants ----------------
#define BSZ   512
#define F66   66
#define TIN   50
#define KS_   10
#define OUTN  25
#define VL    35          // KS + output_n
#define VN    16          // input_n - VL + 1
#define DCTN  20
#define DM    512
#define GCNIN 40

// ---------------- scratch (device globals; no allocation) ----------------
__device__ float g_dct[DCTN * VL];                       // dct_m[:20]  (20 x 35)
__device__ float g_Xk1[(size_t)10240 * 396];             // key conv1 im2col
__device__ float g_key1[(size_t)10240 * 512];            // key conv1 out (b*20+p, d)
__device__ float g_Xk2[(size_t)8192 * 2560];             // key conv2 im2col
__device__ float g_key2[(size_t)8192 * 512];             // key conv2 out (b*16+n, d)
__device__ float g_Xq1[(size_t)2560 * 396];
__device__ float g_q1[(size_t)2560 * 512];               // (b*5+p, d)
__device__ float g_Xq2[(size_t)512 * 2560];
__device__ float g_q[(size_t)512 * 512];                 // (b, d)
__device__ float g_att[BSZ * VN];
__device__ float g_x[(size_t)BSZ * F66 * GCNIN];         // x (b, f66, 40)
__device__ float g_y[(size_t)BSZ * F66 * DM];
__device__ float g_z[(size_t)BSZ * F66 * DM];
__device__ float g_t[(size_t)BSZ * F66 * DM];
__device__ float g_dctout[(size_t)BSZ * F66 * GCNIN];

// ---------------- dct matrix ----------------
__global__ void dct_build() {
    for (int i = threadIdx.x; i < DCTN * VL; i += blockDim.x) {
        int k = i / VL, v = i % VL;
        double w = (k == 0) ? sqrt(1.0 / VL) : sqrt(2.0 / VL);
        g_dct[i] = (float)(w * cos(3.14159265358979323846 * (v + 0.5) * k / VL));
    }
}

// ---------------- im2col for conv1 (input = src/1000) ----------------
// rows: b*npos+p   cols: f*6+t   value: src[b, off+p+t, f] * 1e-3
__global__ void im2col_c1(const float* __restrict__ src, float* __restrict__ X,
                          int npos, int off) {
    size_t total = (size_t)BSZ * npos * 396;
    for (size_t i = (size_t)blockIdx.x * blockDim.x + threadIdx.x; i < total;
         i += (size_t)gridDim.x * blockDim.x) {
        int col = (int)(i % 396);
        size_t r = i / 396;
        int p = (int)(r % npos);
        int b = (int)(r / npos);
        int f = col / 6, tt = col % 6;
        X[i] = src[((size_t)b * TIN + off + p + tt) * F66 + f] * 1e-3f;
    }
}

// ---------------- im2col for conv2 ----------------
// rows: b*npos_out+p  cols: c*5+t   value: in1[(b*npos_in + p+t)*512 + c]
__global__ void im2col_c2(const float* __restrict__ in1, float* __restrict__ X,
                          int npos_out, int npos_in) {
    size_t total = (size_t)BSZ * npos_out * 2560;
    for (size_t i = (size_t)blockIdx.x * blockDim.x + threadIdx.x; i < total;
         i += (size_t)gridDim.x * blockDim.x) {
        int col = (int)(i % 2560);
        size_t r = i / 2560;
        int p = (int)(r % npos_out);
        int b = (int)(r / npos_out);
        int c = col / 5, tt = col % 5;
        X[i] = in1[((size_t)b * npos_in + p + tt) * 512 + c];
    }
}

// ---------------- generic tiled SGEMM with fused epilogue ----------------
// C[M,N] = A[M,K] * op(B).  BT=true: B is [N,K] row-major (B^T).  BT=false: B is [K,N].
// modes: 0 plain, 1 relu, 2 bias+bn+tanh, 3 bias+bn+tanh+resid, 4 bias+resid
struct Epi {
    const float* bias;
    const float* gamma;
    const float* beta;
    const float* resid;
    int mode;
};

#define BM 64
#define BN 64
#define BK 16

template <bool BT>
__global__ void gemm_kernel(const float* __restrict__ A, const float* __restrict__ B,
                            float* __restrict__ C, int M, int N, int K, Epi e) {
    __shared__ float As[BK][BM + 4];
    __shared__ float Bs[BK][BN + 4];
    int bn0 = blockIdx.x * BN;
    int bm0 = blockIdx.y * BM;
    int t = threadIdx.x;           // 256
    int tx = t % 16, ty = t / 16;  // 16x16

    float acc[4][4] = {};

    int am = t / 16;  // 0..15
    int ak = t % 16;

    for (int k0 = 0; k0 < K; k0 += BK) {
#pragma unroll
        for (int i = 0; i < 4; i++) {
            int m = am + 16 * i;
            int row = bm0 + m;
            int k = k0 + ak;
            As[ak][m] = (row < M && k < K) ? A[(size_t)row * K + k] : 0.f;
        }
        if (BT) {
#pragma unroll
            for (int i = 0; i < 4; i++) {
                int n = am + 16 * i;
                int col = bn0 + n;
                int k = k0 + ak;
                Bs[ak][n] = (col < N && k < K) ? B[(size_t)col * K + k] : 0.f;
            }
        } else {
#pragma unroll
            for (int i = 0; i < 4; i++) {
                int kk = t / 64 + 4 * i;
                int n = t % 64;
                int col = bn0 + n;
                int k = k0 + kk;
                Bs[kk][n] = (col < N && k < K) ? B[(size_t)k * N + col] : 0.f;
            }
        }
        __syncthreads();
#pragma unroll
        for (int kk = 0; kk < BK; kk++) {
            float a[4], b[4];
#pragma unroll
            for (int i = 0; i < 4; i++) a[i] = As[kk][ty * 4 + i];
#pragma unroll
            for (int j = 0; j < 4; j++) b[j] = Bs[kk][tx * 4 + j];
#pragma unroll
            for (int i = 0; i < 4; i++)
#pragma unroll
                for (int j = 0; j < 4; j++) acc[i][j] += a[i] * b[j];
        }
        __syncthreads();
    }

    const float invs = 0.9999950000374997f;  // 1/sqrt(1+1e-5)
#pragma unroll
    for (int i = 0; i < 4; i++) {
        int row = bm0 + ty * 4 + i;
        if (row >= M) continue;
        int nmod = row % F66;
#pragma unroll
        for (int j = 0; j < 4; j++) {
            int col = bn0 + tx * 4 + j;
            if (col >= N) continue;
            float v = acc[i][j];
            size_t cidx = (size_t)row * N + col;
            if (e.mode == 1) {
                v = fmaxf(v, 0.f);
            } else if (e.mode == 2 || e.mode == 3) {
                v += e.bias[col];
                int gi = nmod * N + col;
                v = v * e.gamma[gi] * invs + e.beta[gi];
                v = tanhf(v);
                if (e.mode == 3) v += e.resid[cidx];
            } else if (e.mode == 4) {
                v += e.bias[col] + e.resid[cidx];
            }
            C[cidx] = v;
        }
    }
}

// ---------------- attention: score + normalize ----------------
__global__ void score_att_kernel(const float* __restrict__ q,
                                 const float* __restrict__ key2,
                                 float* __restrict__ att) {
    int b = blockIdx.x;
    __shared__ float sc[VN];
    int t = threadIdx.x;
    int w = t / 32, lane = t % 32;
    for (int n = w; n < VN; n += 8) {
        float s = 0.f;
        const float* qp = q + (size_t)b * 512;
        const float* kp = key2 + (size_t)(b * VN + n) * 512;
        for (int d = lane; d < 512; d += 32) s += qp[d] * kp[d];
        for (int o = 16; o; o >>= 1) s += __shfl_xor_sync(0xffffffffu, s, o);
        if (lane == 0) sc[n] = s + 1e-15f;
    }
    __syncthreads();
    float tot = 0.f;
#pragma unroll
    for (int n = 0; n < VN; n++) tot += sc[n];
    if (t < VN) att[b * VN + t] = sc[t] / tot;
}

// ---------------- build x = [dct_in | dct_att]  (b, 66, 40) ----------------
__global__ void x_build(const float* __restrict__ src) {
    int b = blockIdx.x;
    int t = threadIdx.x;  // 256
    __shared__ float ss[TIN * F66];     // src[b]
    __shared__ float sh_s[VL * F66];    // s[v][f]
    __shared__ float sh_dct[DCTN * VL];
    __shared__ float sh_att[VN];

    for (int i = t; i < TIN * F66; i += 256) ss[i] = src[(size_t)b * TIN * F66 + i];
    for (int i = t; i < DCTN * VL; i += 256) sh_dct[i] = g_dct[i];
    if (t < VN) sh_att[t] = g_att[b * VN + t];
    __syncthreads();

    for (int i = t; i < VL * F66; i += 256) {
        int v = i / F66, f = i % F66;
        float a = 0.f;
#pragma unroll
        for (int n = 0; n < VN; n++) a += sh_att[n] * ss[(n + v) * F66 + f];
        sh_s[i] = a;
    }
    __syncthreads();

    for (int i = t; i < F66 * GCNIN; i += 256) {
        int f = i / GCNIN, k = i % GCNIN;
        float a = 0.f;
        if (k < DCTN) {
#pragma unroll
            for (int v = 0; v < VL; v++) {
                int r = (v < KS_) ? (TIN - KS_ + v) : (TIN - 1);
                a += sh_dct[k * VL + v] * ss[r * F66 + f];
            }
        } else {
            int kk = k - DCTN;
#pragma unroll
            for (int v = 0; v < VL; v++) a += sh_dct[kk * VL + v] * sh_s[v * F66 + f];
        }
        g_x[(size_t)b * F66 * GCNIN + i] = a;
    }
}

// ---------------- node mix:  out[b,n,f] = sum_m A[n,m] in[b,m,f] ----------------
__global__ void amix_kernel(const float* __restrict__ A, const float* __restrict__ in,
                            float* __restrict__ out, int F) {
    int b = blockIdx.x;
    int f0 = blockIdx.y * 64;
    __shared__ float Ash[F66 * F66];
    __shared__ float insh[F66][64];
    int t = threadIdx.x;  // 256
    for (int i = t; i < F66 * F66; i += 256) Ash[i] = A[i];
    int fw = F - f0;
    if (fw > 64) fw = 64;
    for (int i = t; i < F66 * 64; i += 256) {
        int m = i / 64, f = i % 64;
        insh[m][f] = (f < fw) ? in[((size_t)b * F66 + m) * F + f0 + f] : 0.f;
    }
    __syncthreads();
    int f = t % 64;
    for (int n = t / 64; n < F66; n += 4) {
        float acc = 0.f;
#pragma unroll 11
        for (int m = 0; m < F66; m++) acc += Ash[n * F66 + m] * insh[m][f];
        if (f < fw) out[((size_t)b * F66 + n) * F + f0 + f] = acc;
    }
}

// ---------------- final iDCT:  out[b,v,f] = sum_k dct[k,v]*dctout[b,f,k] ----------------
__global__ void final_idct(float* __restrict__ out) {
    size_t total = (size_t)BSZ * VL * F66;
    for (size_t i = (size_t)blockIdx.x * blockDim.x + threadIdx.x; i < total;
         i += (size_t)gridDim.x * blockDim.x) {
        int f = (int)(i % F66);
        int v = (int)((i / F66) % VL);
        int b = (int)(i / ((size_t)F66 * VL));
        float a = 0.f;
#pragma unroll
        for (int k = 0; k < DCTN; k++)
            a += g_dct[k * VL + v] * g_dctout[((size_t)b * F66 + f) * GCNIN + k];
        out[i] = a;
    }
}

// ---------------- host launcher ----------------
static float* sym(const void* s) {
    void* p = nullptr;
    cudaGetSymbolAddress(&p, s);
    return (float*)p;
}

extern "C" void kernel_launch(void* const* d_in, const int* in_sizes, int n_in,
                              void* d_out, int out_size) {
    const float* src    = (const float*)d_in[0];
    const float* Wq1    = (const float*)d_in[1];
    const float* Wq2    = (const float*)d_in[2];
    const float* Wk1    = (const float*)d_in[3];
    const float* Wk2    = (const float*)d_in[4];
    const float* gc1_W  = (const float*)d_in[5];
    const float* gc1_att= (const float*)d_in[6];
    const float* gc1_b  = (const float*)d_in[7];
    const float* bn1_g  = (const float*)d_in[8];
    const float* bn1_b  = (const float*)d_in[9];
    const float* gcb_W  = (const float*)d_in[10];
    const float* gcb_att= (const float*)d_in[11];
    const float* gcb_b  = (const float*)d_in[12];
    const float* gcb_bn_g = (const float*)d_in[13];
    const float* gcb_bn_b = (const float*)d_in[14];
    const float* gc7_W  = (const float*)d_in[15];
    const float* gc7_att= (const float*)d_in[16];
    const float* gc7_b  = (const float*)d_in[17];
    float* out = (float*)d_out;

    float* pXk1 = sym(g_Xk1);   float* pk1 = sym(g_key1);
    float* pXk2 = sym(g_Xk2);   float* pk2 = sym(g_key2);
    float* pXq1 = sym(g_Xq1);   float* pq1 = sym(g_q1);
    float* pXq2 = sym(g_Xq2);   float* pq  = sym(g_q);
    float* patt = sym(g_att);
    float* px   = sym(g_x);
    float* py   = sym(g_y);
    float* pz   = sym(g_z);
    float* pt   = sym(g_t);
    float* pdo  = sym(g_dctout);

    Epi ep_relu  = {nullptr, nullptr, nullptr, nullptr, 1};

    dct_build<<<1, 256>>>();

    // --- key conv stack ---
    im2col_c1<<<2048, 256>>>(src, pXk1, 20, 0);
    {
        dim3 g(512 / BN, 10240 / BM);
        gemm_kernel<true><<<g, 256>>>(pXk1, Wk1, pk1, 10240, 512, 396, ep_relu);
    }
    im2col_c2<<<4096, 256>>>(pk1, pXk2, 16, 20);
    {
        dim3 g(512 / BN, 8192 / BM);
        gemm_kernel<true><<<g, 256>>>(pXk2, Wk2, pk2, 8192, 512, 2560, ep_relu);
    }

    // --- query conv stack ---
    im2col_c1<<<1024, 256>>>(src, pXq1, 5, TIN - KS_);
    {
        dim3 g(512 / BN, 2560 / BM);
        gemm_kernel<true><<<g, 256>>>(pXq1, Wq1, pq1, 2560, 512, 396, ep_relu);
    }
    im2col_c2<<<1024, 256>>>(pq1, pXq2, 1, 5);
    {
        dim3 g(512 / BN, 512 / BM);
        gemm_kernel<true><<<g, 256>>>(pXq2, Wq2, pq, 512, 512, 2560, ep_relu);
    }

    // --- attention + x ---
    score_att_kernel<<<BSZ, 256>>>(pq, pk2, patt);
    x_build<<<BSZ, 256>>>(src);

    const int M = BSZ * F66;  // 33792

    // --- gc1 ---
    {
        dim3 ga(BSZ, 1);
        amix_kernel<<<ga, 256>>>(gc1_att, px, pt, GCNIN);
        Epi e = {gc1_b, bn1_g, bn1_b, nullptr, 2};
        dim3 g(512 / BN, M / BM);
        gemm_kernel<false><<<g, 256>>>(pt, gc1_W, py, M, 512, GCNIN, e);
    }

    // --- 2 stages x 2 layers, residual after layer 2 ---
    for (int st = 0; st < 2; st++) {
        for (int l = 0; l < 2; l++) {
            int li = st * 2 + l;
            const float* in  = (l == 0) ? py : pz;
            float*       o   = (l == 0) ? pz : py;
            dim3 ga(BSZ, 512 / 64);
            amix_kernel<<<ga, 256>>>(gcb_att + (size_t)li * F66 * F66, in, pt, 512);
            Epi e = {gcb_b + (size_t)li * 512,
                     gcb_bn_g + (size_t)li * F66 * 512,
                     gcb_bn_b + (size_t)li * F66 * 512,
                     (l == 1) ? py : nullptr,
                     (l == 1) ? 3 : 2};
            dim3 g(512 / BN, M / BM);
            gemm_kernel<false><<<g, 256>>>(pt, gcb_W + (size_t)li * 512 * 512, o,
                                           M, 512, 512, e);
        }
    }

    // --- gc7 (+x residual) ---
    {
        dim3 ga(BSZ, 512 / 64);
        amix_kernel<<<ga, 256>>>(gc7_att, py, pt, 512);
        Epi e = {gc7_b, nullptr, nullptr, px, 4};
        dim3 g(1, M / BM);
        gemm_kernel<false><<<g, 256>>>(pt, gc7_W, pdo, M, GCNIN, 512, e);
    }

    // --- final iDCT ---
    final_idct<<<4620, 256>>>(out);
    (void)in_sizes; (void)n_in; (void)out_size;
}

// round 3
// speedup vs baseline: 1.6974x; 1.6974x over previous
#include <cuda_runtime.h>
#include <cuda_bf16.h>
#include <math.h>
#include <stdint.h>

// ---------------- constants ----------------
#define BSZ   512
#define F66   66
#define TIN   50
#define KS_   10
#define VL    35          // KS + output_n
#define VN    16          // input_n - VL + 1
#define DCTN  20
#define DM    512
#define GCNIN 40
#define MROWS (BSZ * F66) // 33792

// conv K dims (padded to multiples of 32 for tensor path)
#define K1P   448         // 66*6=396 -> 448
#define K2    2560

__device__ __forceinline__ uint32_t smem_u32(const void* p) {
    uint32_t a;
    asm("{ .reg .u64 t; cvta.to.shared.u64 t, %1; cvt.u32.u64 %0, t; }" : "=r"(a) : "l"(p));
    return a;
}

// ---------------- scratch (device globals; no allocation) ----------------
__device__ float g_dct[DCTN * VL];

__device__ __nv_bfloat16 g_Xk1h[(size_t)10240 * K1P];
__device__ __nv_bfloat16 g_Xk1l[(size_t)10240 * K1P];
__device__ __nv_bfloat16 g_Xk2h[(size_t)8192 * K2];
__device__ __nv_bfloat16 g_Xk2l[(size_t)8192 * K2];
__device__ __nv_bfloat16 g_Xq1h[(size_t)2560 * K1P];
__device__ __nv_bfloat16 g_Xq1l[(size_t)2560 * K1P];
__device__ __nv_bfloat16 g_Xq2h[(size_t)512 * K2];
__device__ __nv_bfloat16 g_Xq2l[(size_t)512 * K2];
__device__ __nv_bfloat16 g_Wk1h[(size_t)512 * K1P];
__device__ __nv_bfloat16 g_Wk1l[(size_t)512 * K1P];
__device__ __nv_bfloat16 g_Wk2h[(size_t)512 * K2];
__device__ __nv_bfloat16 g_Wk2l[(size_t)512 * K2];
__device__ __nv_bfloat16 g_Wq1h[(size_t)512 * K1P];
__device__ __nv_bfloat16 g_Wq1l[(size_t)512 * K1P];
__device__ __nv_bfloat16 g_Wq2h[(size_t)512 * K2];
__device__ __nv_bfloat16 g_Wq2l[(size_t)512 * K2];
__device__ __nv_bfloat16 g_Wg1h[(size_t)512 * 64];
__device__ __nv_bfloat16 g_Wg1l[(size_t)512 * 64];
__device__ __nv_bfloat16 g_Wgbh[(size_t)4 * 512 * 512];
__device__ __nv_bfloat16 g_Wgbl[(size_t)4 * 512 * 512];
__device__ __nv_bfloat16 g_Th[(size_t)MROWS * 512];
__device__ __nv_bfloat16 g_Tl[(size_t)MROWS * 512];

__device__ float g_key1[(size_t)10240 * 512];
__device__ float g_key2[(size_t)8192 * 512];
__device__ float g_q1[(size_t)2560 * 512];
__device__ float g_q[(size_t)512 * 512];
__device__ float g_att[BSZ * VN];
__device__ float g_x[(size_t)BSZ * F66 * GCNIN];
__device__ float g_y[(size_t)MROWS * DM];
__device__ float g_z[(size_t)MROWS * DM];
__device__ float g_t[(size_t)MROWS * DM];
__device__ float g_dctout[(size_t)MROWS * GCNIN];

// ---------------- epilogue descriptor ----------------
// modes: 1 relu, 2 bias+bn+tanh, 3 bias+bn+tanh+resid, 4 bias+resid
struct Epi {
    const float* bias;
    const float* gamma;
    const float* beta;
    const float* resid;
    int mode;
};

__device__ __forceinline__ void split_bf16(float v, __nv_bfloat16& h, __nv_bfloat16& l) {
    h = __float2bfloat16_rn(v);
    l = __float2bfloat16_rn(v - __bfloat162float(h));
}

// ---------------- dct matrix ----------------
__global__ void dct_build() {
    for (int i = threadIdx.x; i < DCTN * VL; i += blockDim.x) {
        int k = i / VL, v = i % VL;
        double w = (k == 0) ? sqrt(1.0 / VL) : sqrt(2.0 / VL);
        g_dct[i] = (float)(w * cos(3.14159265358979323846 * (v + 0.5) * k / VL));
    }
}

// ---------------- weight preps ----------------
__global__ void prep_NK(const float* __restrict__ W, __nv_bfloat16* __restrict__ Bh,
                        __nv_bfloat16* __restrict__ Bl, int N, int K, int Kp) {
    size_t total = (size_t)N * Kp;
    for (size_t i = (size_t)blockIdx.x * blockDim.x + threadIdx.x; i < total;
         i += (size_t)gridDim.x * blockDim.x) {
        int k = (int)(i % Kp);
        int n = (int)(i / Kp);
        float v = (k < K) ? W[(size_t)n * K + k] : 0.f;
        __nv_bfloat16 h, l; split_bf16(v, h, l);
        Bh[i] = h; Bl[i] = l;
    }
}

__global__ void prep_KN(const float* __restrict__ W, __nv_bfloat16* __restrict__ Bh,
                        __nv_bfloat16* __restrict__ Bl, int K, int N, int Kp) {
    size_t total = (size_t)N * Kp;
    for (size_t i = (size_t)blockIdx.x * blockDim.x + threadIdx.x; i < total;
         i += (size_t)gridDim.x * blockDim.x) {
        int k = (int)(i % Kp);
        int n = (int)(i / Kp);
        float v = (k < K) ? W[(size_t)k * N + n] : 0.f;
        __nv_bfloat16 h, l; split_bf16(v, h, l);
        Bh[i] = h; Bl[i] = l;
    }
}

// ---------------- im2col conv1 -> hi/lo (K padded to 448) ----------------
__global__ void im2col_c1b(const float* __restrict__ src, __nv_bfloat16* __restrict__ Xh,
                           __nv_bfloat16* __restrict__ Xl, int npos, int off) {
    size_t total = (size_t)BSZ * npos * K1P;
    for (size_t i = (size_t)blockIdx.x * blockDim.x + threadIdx.x; i < total;
         i += (size_t)gridDim.x * blockDim.x) {
        int col = (int)(i % K1P);
        size_t r = i / K1P;
        int p = (int)(r % npos);
        int b = (int)(r / npos);
        float v = 0.f;
        if (col < 396) {
            int f = col / 6, tt = col % 6;
            v = src[((size_t)b * TIN + off + p + tt) * F66 + f] * 1e-3f;
        }
        __nv_bfloat16 h, l; split_bf16(v, h, l);
        Xh[i] = h; Xl[i] = l;
    }
}

// ---------------- im2col conv2 -> hi/lo (K=2560) ----------------
__global__ void im2col_c2b(const float* __restrict__ in1, __nv_bfloat16* __restrict__ Xh,
                           __nv_bfloat16* __restrict__ Xl, int npos_out, int npos_in) {
    size_t total = (size_t)BSZ * npos_out * K2;
    for (size_t i = (size_t)blockIdx.x * blockDim.x + threadIdx.x; i < total;
         i += (size_t)gridDim.x * blockDim.x) {
        int col = (int)(i % K2);
        size_t r = i / K2;
        int p = (int)(r % npos_out);
        int b = (int)(r / npos_out);
        int c = col / 5, tt = col % 5;
        float v = in1[((size_t)b * npos_in + p + tt) * 512 + c];
        __nv_bfloat16 h, l; split_bf16(v, h, l);
        Xh[i] = h; Xl[i] = l;
    }
}

// ---------------- HMMA bf16x3 GEMM (mma.sync, generic PTX) ----------------
// C[M,512] = sum over passes { (Ah,Bh), (Al,Bh), (Ah,Bl) } of A*B^T.
// A: [M,K] bf16 row-major, B: [512,K] bf16 row-major. M%128==0, K%32==0.
// Tile 128x128, BK=32, 8 warps (2m x 4n), each warp 64x32.
#define SROW 40  // smem row stride in bf16 elements (80 bytes)

__device__ __forceinline__ float epi_apply(float v, int col, int nmod, const Epi& e) {
    if (e.mode == 1) return fmaxf(v, 0.f);
    if (e.mode == 2 || e.mode == 3) {
        v += e.bias[col];
        int gi = nmod * 512 + col;
        v = tanhf(v * e.gamma[gi] * 0.9999950000374997f + e.beta[gi]);
    }
    return v;
}

__global__ void __launch_bounds__(256) hgemm(
    const __nv_bfloat16* __restrict__ Ah, const __nv_bfloat16* __restrict__ Al,
    const __nv_bfloat16* __restrict__ Bh, const __nv_bfloat16* __restrict__ Bl,
    float* __restrict__ C, int M, int K, Epi e) {
    __shared__ __align__(16) __nv_bfloat16 sA[2][128 * SROW];
    __shared__ __align__(16) __nv_bfloat16 sB[2][128 * SROW];
    const int tid = threadIdx.x;
    const int bm0 = blockIdx.y * 128;
    const int bn0 = blockIdx.x * 128;
    const int warp = tid >> 5, lane = tid & 31;
    const int wm = warp & 1, wn = warp >> 1;

    const __nv_bfloat16* APs[3] = {Ah, Al, Ah};
    const __nv_bfloat16* BPs[3] = {Bh, Bh, Bl};
    const int KT = K >> 5;
    const int T = 3 * KT;

    float c[4][4][4];
#pragma unroll
    for (int i = 0; i < 4; i++)
#pragma unroll
        for (int j = 0; j < 4; j++)
#pragma unroll
            for (int q = 0; q < 4; q++) c[i][j][q] = 0.f;

    const uint32_t sAa = smem_u32(&sA[0][0]);
    const uint32_t sBa = smem_u32(&sB[0][0]);

#define LOADTILE(buf, kt) do {                                                   \
    const __nv_bfloat16* Ag = APs[(kt) / KT] + (size_t)bm0 * K + (((kt) % KT) << 5); \
    const __nv_bfloat16* Bg = BPs[(kt) / KT] + (size_t)bn0 * K + (((kt) % KT) << 5); \
    _Pragma("unroll")                                                            \
    for (int i = 0; i < 2; i++) {                                                \
        int id = tid + 256 * i;                                                  \
        int r = id >> 2, cc = id & 3;                                            \
        uint32_t sa = sAa + (uint32_t)(buf) * 10240u + (uint32_t)(r * 80 + cc * 16); \
        const void* ga = Ag + (size_t)r * K + cc * 8;                            \
        asm volatile("cp.async.ca.shared.global [%0], [%1], 16;" :: "r"(sa), "l"(ga)); \
        uint32_t sb2 = sBa + (uint32_t)(buf) * 10240u + (uint32_t)(r * 80 + cc * 16); \
        const void* gb = Bg + (size_t)r * K + cc * 8;                            \
        asm volatile("cp.async.ca.shared.global [%0], [%1], 16;" :: "r"(sb2), "l"(gb)); \
    }                                                                            \
    asm volatile("cp.async.commit_group;");                                      \
} while (0)

    LOADTILE(0, 0);
    for (int kt = 0; kt < T; kt++) {
        const int buf = kt & 1;
        if (kt + 1 < T) {
            LOADTILE(buf ^ 1, kt + 1);
            asm volatile("cp.async.wait_group 1;");
        } else {
            asm volatile("cp.async.wait_group 0;");
        }
        __syncthreads();
        const uint32_t Ab = sAa + (uint32_t)buf * 10240u;
        const uint32_t Bb = sBa + (uint32_t)buf * 10240u;
#pragma unroll
        for (int kh = 0; kh < 2; kh++) {
            uint32_t af[4][4], bfr[2][4];
#pragma unroll
            for (int mi = 0; mi < 4; mi++) {
                int row = wm * 64 + mi * 16 + (lane & 7) + ((lane >> 3) & 1) * 8;
                int col = kh * 16 + (lane >> 4) * 8;
                uint32_t ad = Ab + (uint32_t)(row * 80 + col * 2);
                asm volatile("ldmatrix.sync.aligned.m8n8.x4.shared.b16 {%0,%1,%2,%3}, [%4];"
                    : "=r"(af[mi][0]), "=r"(af[mi][1]), "=r"(af[mi][2]), "=r"(af[mi][3])
                    : "r"(ad));
            }
#pragma unroll
            for (int bi = 0; bi < 2; bi++) {
                int row = wn * 32 + bi * 16 + (lane & 7) + (lane >> 4) * 8;
                int col = kh * 16 + ((lane >> 3) & 1) * 8;
                uint32_t bd = Bb + (uint32_t)(row * 80 + col * 2);
                asm volatile("ldmatrix.sync.aligned.m8n8.x4.shared.b16 {%0,%1,%2,%3}, [%4];"
                    : "=r"(bfr[bi][0]), "=r"(bfr[bi][1]), "=r"(bfr[bi][2]), "=r"(bfr[bi][3])
                    : "r"(bd));
            }
#pragma unroll
            for (int mi = 0; mi < 4; mi++)
#pragma unroll
                for (int ni = 0; ni < 4; ni++) {
                    uint32_t b0 = bfr[ni >> 1][(ni & 1) * 2];
                    uint32_t b1 = bfr[ni >> 1][(ni & 1) * 2 + 1];
                    asm volatile(
                        "mma.sync.aligned.m16n8k16.row.col.f32.bf16.bf16.f32 "
                        "{%0,%1,%2,%3}, {%4,%5,%6,%7}, {%8,%9}, {%0,%1,%2,%3};"
                        : "+f"(c[mi][ni][0]), "+f"(c[mi][ni][1]),
                          "+f"(c[mi][ni][2]), "+f"(c[mi][ni][3])
                        : "r"(af[mi][0]), "r"(af[mi][1]), "r"(af[mi][2]), "r"(af[mi][3]),
                          "r"(b0), "r"(b1));
                }
        }
        __syncthreads();
    }
#undef LOADTILE

    // ---- epilogue ----
#pragma unroll
    for (int mi = 0; mi < 4; mi++) {
        int r0 = bm0 + wm * 64 + mi * 16 + (lane >> 2);
        int r1 = r0 + 8;
        int nm0 = r0 % F66, nm1 = r1 % F66;
#pragma unroll
        for (int ni = 0; ni < 4; ni++) {
            int cb = bn0 + wn * 32 + ni * 8 + (lane & 3) * 2;
            size_t i0 = (size_t)r0 * 512 + cb;
            size_t i1 = (size_t)r1 * 512 + cb;
            float v0 = epi_apply(c[mi][ni][0], cb, nm0, e);
            float v1 = epi_apply(c[mi][ni][1], cb + 1, nm0, e);
            float v2 = epi_apply(c[mi][ni][2], cb, nm1, e);
            float v3 = epi_apply(c[mi][ni][3], cb + 1, nm1, e);
            if (e.mode == 3) {
                v0 += e.resid[i0]; v1 += e.resid[i0 + 1];
                v2 += e.resid[i1]; v3 += e.resid[i1 + 1];
            }
            *reinterpret_cast<float2*>(C + i0) = make_float2(v0, v1);
            *reinterpret_cast<float2*>(C + i1) = make_float2(v2, v3);
        }
    }
}

// ---------------- FFMA GEMM for gc7 (N=40) ----------------
#define BM 64
#define BN 64
#define BK 16
__global__ void gemm_ffma(const float* __restrict__ A, const float* __restrict__ B,
                          float* __restrict__ C, int M, int N, int K, Epi e) {
    __shared__ float As[BK][BM + 4];
    __shared__ float Bs[BK][BN + 4];
    int bn0 = blockIdx.x * BN;
    int bm0 = blockIdx.y * BM;
    int t = threadIdx.x;
    int tx = t % 16, ty = t / 16;
    float acc[4][4] = {};
    int am = t / 16, ak = t % 16;
    for (int k0 = 0; k0 < K; k0 += BK) {
#pragma unroll
        for (int i = 0; i < 4; i++) {
            int m = am + 16 * i;
            int row = bm0 + m, k = k0 + ak;
            As[ak][m] = (row < M && k < K) ? A[(size_t)row * K + k] : 0.f;
        }
#pragma unroll
        for (int i = 0; i < 4; i++) {
            int kk = t / 64 + 4 * i;
            int n = t % 64;
            int col = bn0 + n, k = k0 + kk;
            Bs[kk][n] = (col < N && k < K) ? B[(size_t)k * N + col] : 0.f;
        }
        __syncthreads();
#pragma unroll
        for (int kk = 0; kk < BK; kk++) {
            float a[4], b[4];
#pragma unroll
            for (int i = 0; i < 4; i++) a[i] = As[kk][ty * 4 + i];
#pragma unroll
            for (int j = 0; j < 4; j++) b[j] = Bs[kk][tx * 4 + j];
#pragma unroll
            for (int i = 0; i < 4; i++)
#pragma unroll
                for (int j = 0; j < 4; j++) acc[i][j] += a[i] * b[j];
        }
        __syncthreads();
    }
#pragma unroll
    for (int i = 0; i < 4; i++) {
        int row = bm0 + ty * 4 + i;
        if (row >= M) continue;
#pragma unroll
        for (int j = 0; j < 4; j++) {
            int col = bn0 + tx * 4 + j;
            if (col >= N) continue;
            float v = acc[i][j];
            size_t cidx = (size_t)row * N + col;
            if (e.mode == 4) v += e.bias[col] + e.resid[cidx];
            C[cidx] = v;
        }
    }
}

// ---------------- attention: score + normalize ----------------
__global__ void score_att_kernel(const float* __restrict__ q,
                                 const float* __restrict__ key2,
                                 float* __restrict__ att) {
    int b = blockIdx.x;
    __shared__ float sc[VN];
    int t = threadIdx.x;
    int w = t / 32, lane = t % 32;
    for (int n = w; n < VN; n += 8) {
        float s = 0.f;
        const float* qp = q + (size_t)b * 512;
        const float* kp = key2 + (size_t)(b * VN + n) * 512;
        for (int d = lane; d < 512; d += 32) s += qp[d] * kp[d];
        for (int o = 16; o; o >>= 1) s += __shfl_xor_sync(0xffffffffu, s, o);
        if (lane == 0) sc[n] = s + 1e-15f;
    }
    __syncthreads();
    float tot = 0.f;
#pragma unroll
    for (int n = 0; n < VN; n++) tot += sc[n];
    if (t < VN) att[b * VN + t] = sc[t] / tot;
}

// ---------------- build x = [dct_in | dct_att]  (b, 66, 40) ----------------
__global__ void x_build(const float* __restrict__ src) {
    int b = blockIdx.x;
    int t = threadIdx.x;
    __shared__ float ss[TIN * F66];
    __shared__ float sh_s[VL * F66];
    __shared__ float sh_dct[DCTN * VL];
    __shared__ float sh_att[VN];
    for (int i = t; i < TIN * F66; i += 256) ss[i] = src[(size_t)b * TIN * F66 + i];
    for (int i = t; i < DCTN * VL; i += 256) sh_dct[i] = g_dct[i];
    if (t < VN) sh_att[t] = g_att[b * VN + t];
    __syncthreads();
    for (int i = t; i < VL * F66; i += 256) {
        int v = i / F66, f = i % F66;
        float a = 0.f;
#pragma unroll
        for (int n = 0; n < VN; n++) a += sh_att[n] * ss[(n + v) * F66 + f];
        sh_s[i] = a;
    }
    __syncthreads();
    for (int i = t; i < F66 * GCNIN; i += 256) {
        int f = i / GCNIN, k = i % GCNIN;
        float a = 0.f;
        if (k < DCTN) {
#pragma unroll
            for (int v = 0; v < VL; v++) {
                int r = (v < KS_) ? (TIN - KS_ + v) : (TIN - 1);
                a += sh_dct[k * VL + v] * ss[r * F66 + f];
            }
        } else {
            int kk = k - DCTN;
#pragma unroll
            for (int v = 0; v < VL; v++) a += sh_dct[kk * VL + v] * sh_s[v * F66 + f];
        }
        g_x[(size_t)b * F66 * GCNIN + i] = a;
    }
}

// ---------------- node mix (crossbar-optimized) ----------------
// out[b,n,f] = sum_m A[n,m] in[b,m,f].  f-tile 64; lane handles 4 f (float4),
// two n-values per warp share the f-range so insh reads dedup.
__global__ void __launch_bounds__(256) amix2(
    const float* __restrict__ A, const float* __restrict__ in,
    float* __restrict__ outf, __nv_bfloat16* __restrict__ oh,
    __nv_bfloat16* __restrict__ ol, int F, int Kp) {
    int b = blockIdx.x;
    int f0 = blockIdx.y * 64;
    __shared__ float Ash[F66 * F66];
    __shared__ float insh[F66][64];
    int t = threadIdx.x;
    for (int i = t; i < F66 * F66; i += 256) Ash[i] = A[i];
    int fw = F - f0;
    if (fw > 64) fw = 64;
    if (fw < 0) fw = 0;
    for (int i = t; i < F66 * 64; i += 256) {
        int m = i >> 6, f = i & 63;
        insh[m][f] = (f < fw) ? in[((size_t)b * F66 + m) * F + f0 + f] : 0.f;
    }
    __syncthreads();
    int w = t >> 5, lane = t & 31;
    int h = lane >> 4, sub = lane & 15;
    int fl = sub * 4;
#pragma unroll
    for (int pass = 0; pass < 5; pass++) {
        int n = pass * 16 + w * 2 + h;
        int nn = (n < F66) ? n : 0;
        const float* arow = Ash + nn * F66;
        float ax = 0.f, ay = 0.f, az = 0.f, aw = 0.f;
#pragma unroll 6
        for (int m = 0; m < F66; m++) {
            float a = arow[m];
            float4 yv = *reinterpret_cast<const float4*>(&insh[m][fl]);
            ax += a * yv.x; ay += a * yv.y; az += a * yv.z; aw += a * yv.w;
        }
        if (n < F66) {
            float vals[4] = {ax, ay, az, aw};
            if (outf) {
#pragma unroll
                for (int j = 0; j < 4; j++)
                    if (fl + j < fw)
                        outf[((size_t)b * F66 + n) * F + f0 + fl + j] = vals[j];
            }
            if (oh) {
                size_t o = ((size_t)b * F66 + n) * Kp + f0 + fl;
#pragma unroll
                for (int j = 0; j < 4; j++) {
                    float v = (fl + j < fw) ? vals[j] : 0.f;
                    __nv_bfloat16 hh, ll; split_bf16(v, hh, ll);
                    oh[o + j] = hh; ol[o + j] = ll;
                }
            }
        }
    }
}

// ---------------- final iDCT ----------------
__global__ void final_idct(float* __restrict__ out) {
    size_t total = (size_t)BSZ * VL * F66;
    for (size_t i = (size_t)blockIdx.x * blockDim.x + threadIdx.x; i < total;
         i += (size_t)gridDim.x * blockDim.x) {
        int f = (int)(i % F66);
        int v = (int)((i / F66) % VL);
        int b = (int)(i / ((size_t)F66 * VL));
        float a = 0.f;
#pragma unroll
        for (int k = 0; k < DCTN; k++)
            a += g_dct[k * VL + v] * g_dctout[((size_t)b * F66 + f) * GCNIN + k];
        out[i] = a;
    }
}

// ---------------- host launcher ----------------
template <typename T>
static T* sym(const void* s) {
    void* p = nullptr;
    cudaGetSymbolAddress(&p, s);
    return (T*)p;
}

extern "C" void kernel_launch(void* const* d_in, const int* in_sizes, int n_in,
                              void* d_out, int out_size) {
    const float* src     = (const float*)d_in[0];
    const float* Wq1     = (const float*)d_in[1];
    const float* Wq2     = (const float*)d_in[2];
    const float* Wk1     = (const float*)d_in[3];
    const float* Wk2     = (const float*)d_in[4];
    const float* gc1_W   = (const float*)d_in[5];
    const float* gc1_att = (const float*)d_in[6];
    const float* gc1_b   = (const float*)d_in[7];
    const float* bn1_g   = (const float*)d_in[8];
    const float* bn1_b   = (const float*)d_in[9];
    const float* gcb_W   = (const float*)d_in[10];
    const float* gcb_att = (const float*)d_in[11];
    const float* gcb_b   = (const float*)d_in[12];
    const float* gcb_bn_g= (const float*)d_in[13];
    const float* gcb_bn_b= (const float*)d_in[14];
    const float* gc7_W   = (const float*)d_in[15];
    const float* gc7_att = (const float*)d_in[16];
    const float* gc7_b   = (const float*)d_in[17];
    float* out = (float*)d_out;

    __nv_bfloat16* Xk1h = sym<__nv_bfloat16>(g_Xk1h); __nv_bfloat16* Xk1l = sym<__nv_bfloat16>(g_Xk1l);
    __nv_bfloat16* Xk2h = sym<__nv_bfloat16>(g_Xk2h); __nv_bfloat16* Xk2l = sym<__nv_bfloat16>(g_Xk2l);
    __nv_bfloat16* Xq1h = sym<__nv_bfloat16>(g_Xq1h); __nv_bfloat16* Xq1l = sym<__nv_bfloat16>(g_Xq1l);
    __nv_bfloat16* Xq2h = sym<__nv_bfloat16>(g_Xq2h); __nv_bfloat16* Xq2l = sym<__nv_bfloat16>(g_Xq2l);
    __nv_bfloat16* Wk1h = sym<__nv_bfloat16>(g_Wk1h); __nv_bfloat16* Wk1l = sym<__nv_bfloat16>(g_Wk1l);
    __nv_bfloat16* Wk2h = sym<__nv_bfloat16>(g_Wk2h); __nv_bfloat16* Wk2l = sym<__nv_bfloat16>(g_Wk2l);
    __nv_bfloat16* Wq1h = sym<__nv_bfloat16>(g_Wq1h); __nv_bfloat16* Wq1l = sym<__nv_bfloat16>(g_Wq1l);
    __nv_bfloat16* Wq2h = sym<__nv_bfloat16>(g_Wq2h); __nv_bfloat16* Wq2l = sym<__nv_bfloat16>(g_Wq2l);
    __nv_bfloat16* Wg1h = sym<__nv_bfloat16>(g_Wg1h); __nv_bfloat16* Wg1l = sym<__nv_bfloat16>(g_Wg1l);
    __nv_bfloat16* Wgbh = sym<__nv_bfloat16>(g_Wgbh); __nv_bfloat16* Wgbl = sym<__nv_bfloat16>(g_Wgbl);
    __nv_bfloat16* Th   = sym<__nv_bfloat16>(g_Th);   __nv_bfloat16* Tl   = sym<__nv_bfloat16>(g_Tl);

    float* key1 = sym<float>(g_key1);
    float* key2 = sym<float>(g_key2);
    float* q1   = sym<float>(g_q1);
    float* qv   = sym<float>(g_q);
    float* patt = sym<float>(g_att);
    float* px   = sym<float>(g_x);
    float* py   = sym<float>(g_y);
    float* pz   = sym<float>(g_z);
    float* pt   = sym<float>(g_t);
    float* pdo  = sym<float>(g_dctout);

    Epi ep_relu = {nullptr, nullptr, nullptr, nullptr, 1};

    dct_build<<<1, 256>>>();

    // ---- weight preps ----
    prep_NK<<<256, 256>>>(Wk1, Wk1h, Wk1l, 512, 396, K1P);
    prep_NK<<<512, 256>>>(Wk2, Wk2h, Wk2l, 512, K2, K2);
    prep_NK<<<256, 256>>>(Wq1, Wq1h, Wq1l, 512, 396, K1P);
    prep_NK<<<512, 256>>>(Wq2, Wq2h, Wq2l, 512, K2, K2);
    prep_KN<<<64, 256>>>(gc1_W, Wg1h, Wg1l, GCNIN, 512, 64);
    for (int li = 0; li < 4; li++)
        prep_KN<<<256, 256>>>(gcb_W + (size_t)li * 512 * 512,
                              Wgbh + (size_t)li * 512 * 512,
                              Wgbl + (size_t)li * 512 * 512, 512, 512, 512);

    // ---- key conv stack (tensor) ----
    im2col_c1b<<<2048, 256>>>(src, Xk1h, Xk1l, 20, 0);
    hgemm<<<dim3(4, 80), 256>>>(Xk1h, Xk1l, Wk1h, Wk1l, key1, 10240, K1P, ep_relu);
    im2col_c2b<<<4096, 256>>>(key1, Xk2h, Xk2l, 16, 20);
    hgemm<<<dim3(4, 64), 256>>>(Xk2h, Xk2l, Wk2h, Wk2l, key2, 8192, K2, ep_relu);

    // ---- query conv stack (tensor) ----
    im2col_c1b<<<1024, 256>>>(src, Xq1h, Xq1l, 5, TIN - KS_);
    hgemm<<<dim3(4, 20), 256>>>(Xq1h, Xq1l, Wq1h, Wq1l, q1, 2560, K1P, ep_relu);
    im2col_c2b<<<1024, 256>>>(q1, Xq2h, Xq2l, 1, 5);
    hgemm<<<dim3(4, 4), 256>>>(Xq2h, Xq2l, Wq2h, Wq2l, qv, 512, K2, ep_relu);

    // ---- attention + x ----
    score_att_kernel<<<BSZ, 256>>>(qv, key2, patt);
    x_build<<<BSZ, 256>>>(src);

    const int M = MROWS;

    // ---- gc1 (tensor, K padded 40->64) ----
    {
        amix2<<<dim3(BSZ, 1), 256>>>(gc1_att, px, nullptr, Th, Tl, GCNIN, 64);
        Epi e = {gc1_b, bn1_g, bn1_b, nullptr, 2};
        hgemm<<<dim3(4, M / 128), 256>>>(Th, Tl, Wg1h, Wg1l, py, M, 64, e);
    }

    // ---- 2 stages x 2 layers, residual after layer 2 ----
    for (int st = 0; st < 2; st++) {
        for (int l = 0; l < 2; l++) {
            int li = st * 2 + l;
            const float* in = (l == 0) ? py : pz;
            float* o = (l == 0) ? pz : py;
            amix2<<<dim3(BSZ, 8), 256>>>(gcb_att + (size_t)li * F66 * F66, in,
                                         nullptr, Th, Tl, 512, 512);
            Epi e = {gcb_b + (size_t)li * 512,
                     gcb_bn_g + (size_t)li * F66 * 512,
                     gcb_bn_b + (size_t)li * F66 * 512,
                     (l == 1) ? py : nullptr,
                     (l == 1) ? 3 : 2};
            hgemm<<<dim3(4, M / 128), 256>>>(Th, Tl,
                Wgbh + (size_t)li * 512 * 512, Wgbl + (size_t)li * 512 * 512, o, M, 512, e);
        }
    }

    // ---- gc7 (+x residual), FFMA (N=40) ----
    {
        amix2<<<dim3(BSZ, 8), 256>>>(gc7_att, py, pt, nullptr, nullptr, 512, 512);
        Epi e = {gc7_b, nullptr, nullptr, px, 4};
        gemm_ffma<<<dim3(1, M / BM), 256>>>(pt, gc7_W, pdo, M, GCNIN, 512, e);
    }

    // ---- final iDCT ----
    final_idct<<<4620, 256>>>(out);
    (void)in_sizes; (void)n_in; (void)out_size;
}

// round 5
// speedup vs baseline: 2.3575x; 1.3888x over previous
#include <cuda_runtime.h>
#include <cuda_bf16.h>
#include <math.h>
#include <stdint.h>

// ---------------- constants ----------------
#define BSZ   512
#define F66   66
#define TIN   50
#define KS_   10
#define VL    35          // KS + output_n
#define VN    16          // input_n - VL + 1
#define DCTN  20
#define DM    512
#define GCNIN 40
#define MROWS (BSZ * F66) // 33792

#define K1P   448         // 66*6=396 -> 448
#define K2    2560

__device__ __forceinline__ uint32_t smem_u32(const void* p) {
    uint32_t a;
    asm("{ .reg .u64 t; cvta.to.shared.u64 t, %1; cvt.u32.u64 %0, t; }" : "=r"(a) : "l"(p));
    return a;
}

__device__ __forceinline__ void mma16816(float* c, const uint32_t* a, uint32_t b0, uint32_t b1) {
    asm volatile(
        "mma.sync.aligned.m16n8k16.row.col.f32.bf16.bf16.f32 "
        "{%0,%1,%2,%3}, {%4,%5,%6,%7}, {%8,%9}, {%0,%1,%2,%3};"
        : "+f"(c[0]), "+f"(c[1]), "+f"(c[2]), "+f"(c[3])
        : "r"(a[0]), "r"(a[1]), "r"(a[2]), "r"(a[3]), "r"(b0), "r"(b1));
}

#define LDSM4(r, addr) \
    asm volatile("ldmatrix.sync.aligned.m8n8.x4.shared.b16 {%0,%1,%2,%3}, [%4];" \
        : "=r"((r)[0]), "=r"((r)[1]), "=r"((r)[2]), "=r"((r)[3]) : "r"(addr))

#define LDSM4T(r, addr) \
    asm volatile("ldmatrix.sync.aligned.m8n8.x4.trans.shared.b16 {%0,%1,%2,%3}, [%4];" \
        : "=r"((r)[0]), "=r"((r)[1]), "=r"((r)[2]), "=r"((r)[3]) : "r"(addr))

#define CPA16(saddr, gptr) \
    asm volatile("cp.async.ca.shared.global [%0], [%1], 16;" :: "r"(saddr), "l"(gptr))

// ---------------- scratch (device globals; no allocation) ----------------
__device__ float g_dct[DCTN * VL];

__device__ __nv_bfloat16 g_Xk1h[(size_t)10240 * K1P];
__device__ __nv_bfloat16 g_Xk1l[(size_t)10240 * K1P];
__device__ __nv_bfloat16 g_Xk2h[(size_t)8192 * K2];
__device__ __nv_bfloat16 g_Xk2l[(size_t)8192 * K2];
__device__ __nv_bfloat16 g_Xq1h[(size_t)2560 * K1P];
__device__ __nv_bfloat16 g_Xq1l[(size_t)2560 * K1P];
__device__ __nv_bfloat16 g_Xq2h[(size_t)512 * K2];
__device__ __nv_bfloat16 g_Xq2l[(size_t)512 * K2];
__device__ __nv_bfloat16 g_Wk1h[(size_t)512 * K1P];
__device__ __nv_bfloat16 g_Wk1l[(size_t)512 * K1P];
__device__ __nv_bfloat16 g_Wk2h[(size_t)512 * K2];
__device__ __nv_bfloat16 g_Wk2l[(size_t)512 * K2];
__device__ __nv_bfloat16 g_Wq1h[(size_t)512 * K1P];
__device__ __nv_bfloat16 g_Wq1l[(size_t)512 * K1P];
__device__ __nv_bfloat16 g_Wq2h[(size_t)512 * K2];
__device__ __nv_bfloat16 g_Wq2l[(size_t)512 * K2];
__device__ __nv_bfloat16 g_Wg1h[(size_t)512 * 64];
__device__ __nv_bfloat16 g_Wg1l[(size_t)512 * 64];
__device__ __nv_bfloat16 g_Wgbh[(size_t)4 * 512 * 512];
__device__ __nv_bfloat16 g_Wgbl[(size_t)4 * 512 * 512];
__device__ __nv_bfloat16 g_Th[(size_t)MROWS * 512];
__device__ __nv_bfloat16 g_Tl[(size_t)MROWS * 512];
__device__ __nv_bfloat16 g_yh[(size_t)MROWS * 512];
__device__ __nv_bfloat16 g_yl[(size_t)MROWS * 512];
__device__ __nv_bfloat16 g_zh[(size_t)MROWS * 512];
__device__ __nv_bfloat16 g_zl[(size_t)MROWS * 512];
__device__ __nv_bfloat16 g_Aph[5 * 80 * 80];  // padded att matrices hi (4 gcb + gc7)
__device__ __nv_bfloat16 g_Apl[5 * 80 * 80];

__device__ float g_key1[(size_t)10240 * 512];
__device__ float g_key2[(size_t)8192 * 512];
__device__ float g_q1[(size_t)2560 * 512];
__device__ float g_q[(size_t)512 * 512];
__device__ float g_att[BSZ * VN];
__device__ float g_x[(size_t)BSZ * F66 * GCNIN];
__device__ float g_y[(size_t)MROWS * DM];
__device__ float g_z[(size_t)MROWS * DM];
__device__ float g_t[(size_t)MROWS * DM];
__device__ float g_dctout[(size_t)MROWS * GCNIN];

// ---------------- epilogue descriptor ----------------
// modes: 1 relu, 2 bias+bn+tanh, 3 bias+bn+tanh+resid
struct Epi {
    const float* bias;
    const float* gamma;
    const float* beta;
    const float* resid;
    int mode;
};

__device__ __forceinline__ void split_bf16(float v, __nv_bfloat16& h, __nv_bfloat16& l) {
    h = __float2bfloat16_rn(v);
    l = __float2bfloat16_rn(v - __bfloat162float(h));
}

__device__ __forceinline__ uint32_t pack2(float a, float b, bool lo) {
    __nv_bfloat16 ha, la, hb, lb;
    split_bf16(a, ha, la); split_bf16(b, hb, lb);
    uint16_t x = lo ? __bfloat16_as_ushort(la) : __bfloat16_as_ushort(ha);
    uint16_t y = lo ? __bfloat16_as_ushort(lb) : __bfloat16_as_ushort(hb);
    return (uint32_t)x | ((uint32_t)y << 16);
}

// ---------------- dct matrix ----------------
__global__ void dct_build() {
    for (int i = threadIdx.x; i < DCTN * VL; i += blockDim.x) {
        int k = i / VL, v = i % VL;
        double w = (k == 0) ? sqrt(1.0 / VL) : sqrt(2.0 / VL);
        g_dct[i] = (float)(w * cos(3.14159265358979323846 * (v + 0.5) * k / VL));
    }
}

// ---------------- weight preps ----------------
__global__ void prep_NK(const float* __restrict__ W, __nv_bfloat16* __restrict__ Bh,
                        __nv_bfloat16* __restrict__ Bl, int N, int K, int Kp) {
    size_t total = (size_t)N * Kp;
    for (size_t i = (size_t)blockIdx.x * blockDim.x + threadIdx.x; i < total;
         i += (size_t)gridDim.x * blockDim.x) {
        int k = (int)(i % Kp);
        int n = (int)(i / Kp);
        float v = (k < K) ? W[(size_t)n * K + k] : 0.f;
        __nv_bfloat16 h, l; split_bf16(v, h, l);
        Bh[i] = h; Bl[i] = l;
    }
}

__global__ void prep_KN(const float* __restrict__ W, __nv_bfloat16* __restrict__ Bh,
                        __nv_bfloat16* __restrict__ Bl, int K, int N, int Kp) {
    size_t total = (size_t)N * Kp;
    for (size_t i = (size_t)blockIdx.x * blockDim.x + threadIdx.x; i < total;
         i += (size_t)gridDim.x * blockDim.x) {
        int k = (int)(i % Kp);
        int n = (int)(i / Kp);
        float v = (k < K) ? W[(size_t)k * N + n] : 0.f;
        __nv_bfloat16 h, l; split_bf16(v, h, l);
        Bh[i] = h; Bl[i] = l;
    }
}

// pad 5 att matrices (4 gcb + gc7) 66x66 -> 80x80 hi/lo
__global__ void prep_att(const float* __restrict__ gcb_att, const float* __restrict__ gc7_att) {
    int total = 5 * 80 * 80;
    for (int i = blockIdx.x * blockDim.x + threadIdx.x; i < total; i += gridDim.x * blockDim.x) {
        int li = i / 6400, rem = i % 6400;
        int r = rem / 80, c = rem % 80;
        float v = 0.f;
        if (r < F66 && c < F66) {
            const float* src = (li < 4) ? (gcb_att + (size_t)li * F66 * F66) : gc7_att;
            v = src[r * F66 + c];
        }
        __nv_bfloat16 h, l; split_bf16(v, h, l);
        g_Aph[i] = h; g_Apl[i] = l;
    }
}

// ---------------- im2col conv1 -> hi/lo ----------------
__global__ void im2col_c1b(const float* __restrict__ src, __nv_bfloat16* __restrict__ Xh,
                           __nv_bfloat16* __restrict__ Xl, int npos, int off) {
    size_t total = (size_t)BSZ * npos * K1P;
    for (size_t i = (size_t)blockIdx.x * blockDim.x + threadIdx.x; i < total;
         i += (size_t)gridDim.x * blockDim.x) {
        int col = (int)(i % K1P);
        size_t r = i / K1P;
        int p = (int)(r % npos);
        int b = (int)(r / npos);
        float v = 0.f;
        if (col < 396) {
            int f = col / 6, tt = col % 6;
            v = src[((size_t)b * TIN + off + p + tt) * F66 + f] * 1e-3f;
        }
        __nv_bfloat16 h, l; split_bf16(v, h, l);
        Xh[i] = h; Xl[i] = l;
    }
}

// ---------------- im2col conv2 -> hi/lo ----------------
__global__ void im2col_c2b(const float* __restrict__ in1, __nv_bfloat16* __restrict__ Xh,
                           __nv_bfloat16* __restrict__ Xl, int npos_out, int npos_in) {
    size_t total = (size_t)BSZ * npos_out * K2;
    for (size_t i = (size_t)blockIdx.x * blockDim.x + threadIdx.x; i < total;
         i += (size_t)gridDim.x * blockDim.x) {
        int col = (int)(i % K2);
        size_t r = i / K2;
        int p = (int)(r % npos_out);
        int b = (int)(r / npos_out);
        int c = col / 5, tt = col % 5;
        float v = in1[((size_t)b * npos_in + p + tt) * 512 + c];
        __nv_bfloat16 h, l; split_bf16(v, h, l);
        Xh[i] = h; Xl[i] = l;
    }
}

// ---------------- HMMA bf16x3 GEMM, interleaved passes, 128x256 tile ----------------
// C[M,512] = (Ah+Al)*(Bh)^T + Ah*(Bl)^T  (fp32 accum). M%128==0, K%32==0.
// 512 threads = 16 warps (2m x 8n); warp tile 64x32; BK=32 double-buffered.
// SMEM per buf: Ah 10240 | Al 10240 | Bh 20480 | Bl 20480 = 61440; x2 = 122880.
#define HG_SMEM 122880

__device__ __forceinline__ float epi_apply(float v, int col, int nmod, const Epi& e) {
    if (e.mode == 1) return fmaxf(v, 0.f);
    if (e.mode == 2 || e.mode == 3) {
        v += e.bias[col];
        int gi = nmod * 512 + col;
        v = tanhf(v * e.gamma[gi] * 0.9999950000374997f + e.beta[gi]);
    }
    return v;
}

__global__ void __launch_bounds__(512) hgemm(
    const __nv_bfloat16* __restrict__ Ah, const __nv_bfloat16* __restrict__ Al,
    const __nv_bfloat16* __restrict__ Bh, const __nv_bfloat16* __restrict__ Bl,
    float* __restrict__ C, __nv_bfloat16* __restrict__ Ch, __nv_bfloat16* __restrict__ Cl,
    int M, int K, Epi e) {
    extern __shared__ __align__(16) char smem[];
    const uint32_t sb = smem_u32(smem);
    const int tid = threadIdx.x;
    const int bm0 = blockIdx.y * 128;
    const int bn0 = blockIdx.x * 256;
    const int warp = tid >> 5, lane = tid & 31;
    const int wm = warp & 1, wn = warp >> 1;
    const int KT = K >> 5;

    float c[4][4][4];
#pragma unroll
    for (int i = 0; i < 4; i++)
#pragma unroll
        for (int j = 0; j < 4; j++)
#pragma unroll
            for (int q = 0; q < 4; q++) c[i][j][q] = 0.f;

#define HLOAD(buf, kt) do {                                                        \
    const int k0 = (kt) << 5;                                                      \
    {                                                                              \
        int r = tid >> 2, cc = tid & 3;                                            \
        uint32_t so = sb + (uint32_t)(buf) * 61440u + (uint32_t)(r * 80 + cc * 16);\
        CPA16(so, Ah + (size_t)(bm0 + r) * K + k0 + cc * 8);                       \
        CPA16(so + 10240u, Al + (size_t)(bm0 + r) * K + k0 + cc * 8);              \
    }                                                                              \
    _Pragma("unroll")                                                              \
    for (int i = 0; i < 2; i++) {                                                  \
        int id = tid + 512 * i;                                                    \
        int r = id >> 2, cc = id & 3;                                              \
        uint32_t so = sb + (uint32_t)(buf) * 61440u + 20480u + (uint32_t)(r * 80 + cc * 16); \
        CPA16(so, Bh + (size_t)(bn0 + r) * K + k0 + cc * 8);                       \
        CPA16(so + 20480u, Bl + (size_t)(bn0 + r) * K + k0 + cc * 8);              \
    }                                                                              \
    asm volatile("cp.async.commit_group;");                                        \
} while (0)

    HLOAD(0, 0);
    for (int kt = 0; kt < KT; kt++) {
        const int buf = kt & 1;
        if (kt + 1 < KT) {
            HLOAD(buf ^ 1, kt + 1);
            asm volatile("cp.async.wait_group 1;");
        } else {
            asm volatile("cp.async.wait_group 0;");
        }
        __syncthreads();
        const uint32_t base = sb + (uint32_t)buf * 61440u;
#pragma unroll
        for (int kh = 0; kh < 2; kh++) {
            uint32_t ah[4][4], al[4][4], bh2[2][4], bl2[2][4];
#pragma unroll
            for (int mi = 0; mi < 4; mi++) {
                int row = wm * 64 + mi * 16 + (lane & 7) + ((lane >> 3) & 1) * 8;
                int col = kh * 16 + (lane >> 4) * 8;
                uint32_t ad = base + (uint32_t)(row * 80 + col * 2);
                LDSM4(ah[mi], ad);
                LDSM4(al[mi], ad + 10240u);
            }
#pragma unroll
            for (int bi = 0; bi < 2; bi++) {
                int row = wn * 32 + bi * 16 + (lane & 7) + (lane >> 4) * 8;
                int col = kh * 16 + ((lane >> 3) & 1) * 8;
                uint32_t bd = base + 20480u + (uint32_t)(row * 80 + col * 2);
                LDSM4(bh2[bi], bd);
                LDSM4(bl2[bi], bd + 20480u);
            }
#pragma unroll
            for (int mi = 0; mi < 4; mi++)
#pragma unroll
                for (int ni = 0; ni < 4; ni++) {
                    uint32_t b0h = bh2[ni >> 1][(ni & 1) * 2];
                    uint32_t b1h = bh2[ni >> 1][(ni & 1) * 2 + 1];
                    uint32_t b0l = bl2[ni >> 1][(ni & 1) * 2];
                    uint32_t b1l = bl2[ni >> 1][(ni & 1) * 2 + 1];
                    mma16816(c[mi][ni], ah[mi], b0h, b1h);
                    mma16816(c[mi][ni], al[mi], b0h, b1h);
                    mma16816(c[mi][ni], ah[mi], b0l, b1l);
                }
        }
        __syncthreads();
    }
#undef HLOAD

    // ---- epilogue ----
#pragma unroll
    for (int mi = 0; mi < 4; mi++) {
        int r0 = bm0 + wm * 64 + mi * 16 + (lane >> 2);
        int r1 = r0 + 8;
        int nm0 = r0 % F66, nm1 = r1 % F66;
#pragma unroll
        for (int ni = 0; ni < 4; ni++) {
            int cb = bn0 + wn * 32 + ni * 8 + (lane & 3) * 2;
            size_t i0 = (size_t)r0 * 512 + cb;
            size_t i1 = (size_t)r1 * 512 + cb;
            float v0 = epi_apply(c[mi][ni][0], cb, nm0, e);
            float v1 = epi_apply(c[mi][ni][1], cb + 1, nm0, e);
            float v2 = epi_apply(c[mi][ni][2], cb, nm1, e);
            float v3 = epi_apply(c[mi][ni][3], cb + 1, nm1, e);
            if (e.mode == 3) {
                v0 += e.resid[i0]; v1 += e.resid[i0 + 1];
                v2 += e.resid[i1]; v3 += e.resid[i1 + 1];
            }
            *reinterpret_cast<float2*>(C + i0) = make_float2(v0, v1);
            *reinterpret_cast<float2*>(C + i1) = make_float2(v2, v3);
            if (Ch) {
                *reinterpret_cast<uint32_t*>(Ch + i0) = pack2(v0, v1, false);
                *reinterpret_cast<uint32_t*>(Cl + i0) = pack2(v0, v1, true);
                *reinterpret_cast<uint32_t*>(Ch + i1) = pack2(v2, v3, false);
                *reinterpret_cast<uint32_t*>(Cl + i1) = pack2(v2, v3, true);
            }
        }
    }
}

// ---------------- batched node-mix via HMMA ----------------
// T[b,n,f] = sum_m Aatt[n,m] y[b,m,f]; Aatt padded [80][80] hi/lo; y bf16 hi/lo.
// grid (4 col-tiles of 128, BSZ batches); 256 threads = 8 warps, warp = 16 cols.
// SMEM: A_h [80][88] (14080B) | A_l (14080) | Y_h [80][136] (21760) | Y_l (21760) = 71680.
#define AM_SMEM 71680

__global__ void __launch_bounds__(256) amix_mma(
    const __nv_bfloat16* __restrict__ Aph, const __nv_bfloat16* __restrict__ Apl,
    const __nv_bfloat16* __restrict__ Yh, const __nv_bfloat16* __restrict__ Yl,
    __nv_bfloat16* __restrict__ Th, __nv_bfloat16* __restrict__ Tl,
    float* __restrict__ Tf) {
    extern __shared__ __align__(16) char smem[];
    const uint32_t sb = smem_u32(smem);
    const int b = blockIdx.y;
    const int f0 = blockIdx.x * 128;
    const int tid = threadIdx.x;
    const int warp = tid >> 5, lane = tid & 31;

    // load A (80x80 -> stride 88 elems) hi/lo
    for (int i = tid; i < 800; i += 256) {
        int r = i / 10, cc = i % 10;
        uint32_t dst = sb + (uint32_t)(r * 176 + cc * 16);
        CPA16(dst, Aph + r * 80 + cc * 8);
        CPA16(dst + 14080u, Apl + r * 80 + cc * 8);
    }
    // load Y rows 0..65 (cols f0..f0+127 -> stride 136 elems) hi/lo
    // 128 cols = 256 bytes per row = 16 chunks of 16B
    for (int i = tid; i < 1056; i += 256) {
        int r = i >> 4, cc = i & 15;
        uint32_t dst = sb + 28160u + (uint32_t)(r * 272 + cc * 16);
        const size_t gsrc = ((size_t)b * F66 + r) * 512 + f0 + cc * 8;
        CPA16(dst, Yh + gsrc);
        CPA16(dst + 21760u, Yl + gsrc);
    }
    asm volatile("cp.async.commit_group;");
    // zero pad rows 66..79 of Y (both h/l)
    for (int i = tid; i < 224; i += 256) {
        int r = 66 + (i >> 4), cc = i & 15;
        uint32_t dst = sb + 28160u + (uint32_t)(r * 272 + cc * 16);
        asm volatile("st.shared.v4.b32 [%0], {%1,%1,%1,%1};" :: "r"(dst), "r"(0u));
        asm volatile("st.shared.v4.b32 [%0], {%1,%1,%1,%1};" :: "r"(dst + 21760u), "r"(0u));
    }
    asm volatile("cp.async.wait_group 0;");
    __syncthreads();

    const int n0c = warp * 16;
    uint32_t bh[5][4], bl[5][4];
#pragma unroll
    for (int kt = 0; kt < 5; kt++) {
        int row = kt * 16 + ((lane >> 3) & 1) * 8 + (lane & 7);
        int col = n0c + (lane >> 4) * 8;
        uint32_t ad = sb + 28160u + (uint32_t)(row * 272 + col * 2);
        LDSM4T(bh[kt], ad);
        LDSM4T(bl[kt], ad + 21760u);
    }

    float c[5][2][4];
#pragma unroll
    for (int mi = 0; mi < 5; mi++)
#pragma unroll
        for (int g = 0; g < 2; g++)
#pragma unroll
            for (int q = 0; q < 4; q++) c[mi][g][q] = 0.f;

#pragma unroll
    for (int mi = 0; mi < 5; mi++) {
#pragma unroll
        for (int kt = 0; kt < 5; kt++) {
            int row = mi * 16 + (lane & 7) + ((lane >> 3) & 1) * 8;
            int col = kt * 16 + (lane >> 4) * 8;
            uint32_t ad = sb + (uint32_t)(row * 176 + col * 2);
            uint32_t ah[4], al[4];
            LDSM4(ah, ad);
            LDSM4(al, ad + 14080u);
#pragma unroll
            for (int g = 0; g < 2; g++) {
                mma16816(c[mi][g], ah, bh[kt][g * 2], bh[kt][g * 2 + 1]);
                mma16816(c[mi][g], al, bh[kt][g * 2], bh[kt][g * 2 + 1]);
                mma16816(c[mi][g], ah, bl[kt][g * 2], bl[kt][g * 2 + 1]);
            }
        }
    }

    // epilogue
#pragma unroll
    for (int mi = 0; mi < 5; mi++) {
        int n_0 = mi * 16 + (lane >> 2);
        int n_1 = n_0 + 8;
#pragma unroll
        for (int g = 0; g < 2; g++) {
            int f = f0 + n0c + g * 8 + (lane & 3) * 2;
            if (n_0 < F66) {
                size_t o = ((size_t)b * F66 + n_0) * 512 + f;
                if (Tf) {
                    *reinterpret_cast<float2*>(Tf + o) = make_float2(c[mi][g][0], c[mi][g][1]);
                } else {
                    *reinterpret_cast<uint32_t*>(Th + o) = pack2(c[mi][g][0], c[mi][g][1], false);
                    *reinterpret_cast<uint32_t*>(Tl + o) = pack2(c[mi][g][0], c[mi][g][1], true);
                }
            }
            if (n_1 < F66) {
                size_t o = ((size_t)b * F66 + n_1) * 512 + f;
                if (Tf) {
                    *reinterpret_cast<float2*>(Tf + o) = make_float2(c[mi][g][2], c[mi][g][3]);
                } else {
                    *reinterpret_cast<uint32_t*>(Th + o) = pack2(c[mi][g][2], c[mi][g][3], false);
                    *reinterpret_cast<uint32_t*>(Tl + o) = pack2(c[mi][g][2], c[mi][g][3], true);
                }
            }
        }
    }
}

// ---------------- FFMA GEMM for gc7 (N=40) ----------------
#define BM 64
#define BN 64
#define BK 16
__global__ void gemm_ffma(const float* __restrict__ A, const float* __restrict__ B,
                          float* __restrict__ C, int M, int N, int K,
                          const float* __restrict__ bias, const float* __restrict__ resid) {
    __shared__ float As[BK][BM + 4];
    __shared__ float Bs[BK][BN + 4];
    int bn0 = blockIdx.x * BN;
    int bm0 = blockIdx.y * BM;
    int t = threadIdx.x;
    int tx = t % 16, ty = t / 16;
    float acc[4][4] = {};
    int am = t / 16, ak = t % 16;
    for (int k0 = 0; k0 < K; k0 += BK) {
#pragma unroll
        for (int i = 0; i < 4; i++) {
            int m = am + 16 * i;
            int row = bm0 + m, k = k0 + ak;
            As[ak][m] = (row < M && k < K) ? A[(size_t)row * K + k] : 0.f;
        }
#pragma unroll
        for (int i = 0; i < 4; i++) {
            int kk = t / 64 + 4 * i;
            int n = t % 64;
            int col = bn0 + n, k = k0 + kk;
            Bs[kk][n] = (col < N && k < K) ? B[(size_t)k * N + col] : 0.f;
        }
        __syncthreads();
#pragma unroll
        for (int kk = 0; kk < BK; kk++) {
            float a[4], bb[4];
#pragma unroll
            for (int i = 0; i < 4; i++) a[i] = As[kk][ty * 4 + i];
#pragma unroll
            for (int j = 0; j < 4; j++) bb[j] = Bs[kk][tx * 4 + j];
#pragma unroll
            for (int i = 0; i < 4; i++)
#pragma unroll
                for (int j = 0; j < 4; j++) acc[i][j] += a[i] * bb[j];
        }
        __syncthreads();
    }
#pragma unroll
    for (int i = 0; i < 4; i++) {
        int row = bm0 + ty * 4 + i;
        if (row >= M) continue;
#pragma unroll
        for (int j = 0; j < 4; j++) {
            int col = bn0 + tx * 4 + j;
            if (col >= N) continue;
            size_t cidx = (size_t)row * N + col;
            C[cidx] = acc[i][j] + bias[col] + resid[cidx];
        }
    }
}

// ---------------- attention: score + normalize ----------------
__global__ void score_att_kernel(const float* __restrict__ q,
                                 const float* __restrict__ key2,
                                 float* __restrict__ att) {
    int b = blockIdx.x;
    __shared__ float sc[VN];
    int t = threadIdx.x;
    int w = t / 32, lane = t % 32;
    for (int n = w; n < VN; n += 8) {
        float s = 0.f;
        const float* qp = q + (size_t)b * 512;
        const float* kp = key2 + (size_t)(b * VN + n) * 512;
        for (int d = lane; d < 512; d += 32) s += qp[d] * kp[d];
        for (int o = 16; o; o >>= 1) s += __shfl_xor_sync(0xffffffffu, s, o);
        if (lane == 0) sc[n] = s + 1e-15f;
    }
    __syncthreads();
    float tot = 0.f;
#pragma unroll
    for (int n = 0; n < VN; n++) tot += sc[n];
    if (t < VN) att[b * VN + t] = sc[t] / tot;
}

// ---------------- build x = [dct_in | dct_att]  (b, 66, 40) ----------------
__global__ void x_build(const float* __restrict__ src) {
    int b = blockIdx.x;
    int t = threadIdx.x;
    __shared__ float ss[TIN * F66];
    __shared__ float sh_s[VL * F66];
    __shared__ float sh_dct[DCTN * VL];
    __shared__ float sh_att[VN];
    for (int i = t; i < TIN * F66; i += 256) ss[i] = src[(size_t)b * TIN * F66 + i];
    for (int i = t; i < DCTN * VL; i += 256) sh_dct[i] = g_dct[i];
    if (t < VN) sh_att[t] = g_att[b * VN + t];
    __syncthreads();
    for (int i = t; i < VL * F66; i += 256) {
        int v = i / F66, f = i % F66;
        float a = 0.f;
#pragma unroll
        for (int n = 0; n < VN; n++) a += sh_att[n] * ss[(n + v) * F66 + f];
        sh_s[i] = a;
    }
    __syncthreads();
    for (int i = t; i < F66 * GCNIN; i += 256) {
        int f = i / GCNIN, k = i % GCNIN;
        float a = 0.f;
        if (k < DCTN) {
#pragma unroll
            for (int v = 0; v < VL; v++) {
                int r = (v < KS_) ? (TIN - KS_ + v) : (TIN - 1);
                a += sh_dct[k * VL + v] * ss[r * F66 + f];
            }
        } else {
            int kk = k - DCTN;
#pragma unroll
            for (int v = 0; v < VL; v++) a += sh_dct[kk * VL + v] * sh_s[v * F66 + f];
        }
        g_x[(size_t)b * F66 * GCNIN + i] = a;
    }
}

// ---------------- scalar node mix for gc1 (F=40 -> Th/Tl Kp=64) ----------------
__global__ void __launch_bounds__(256) amix2(
    const float* __restrict__ A, const float* __restrict__ in,
    __nv_bfloat16* __restrict__ oh, __nv_bfloat16* __restrict__ ol, int F, int Kp) {
    int b = blockIdx.x;
    __shared__ float Ash[F66 * F66];
    __shared__ float insh[F66][64];
    int t = threadIdx.x;
    for (int i = t; i < F66 * F66; i += 256) Ash[i] = A[i];
    int fw = F;
    for (int i = t; i < F66 * 64; i += 256) {
        int m = i >> 6, f = i & 63;
        insh[m][f] = (f < fw) ? in[((size_t)b * F66 + m) * F + f] : 0.f;
    }
    __syncthreads();
    int w = t >> 5, lane = t & 31;
    int h = lane >> 4, sub = lane & 15;
    int fl = sub * 4;
#pragma unroll
    for (int pass = 0; pass < 5; pass++) {
        int n = pass * 16 + w * 2 + h;
        int nn = (n < F66) ? n : 0;
        const float* arow = Ash + nn * F66;
        float ax = 0.f, ay = 0.f, az = 0.f, aw = 0.f;
#pragma unroll 6
        for (int m = 0; m < F66; m++) {
            float a = arow[m];
            float4 yv = *reinterpret_cast<const float4*>(&insh[m][fl]);
            ax += a * yv.x; ay += a * yv.y; az += a * yv.z; aw += a * yv.w;
        }
        if (n < F66) {
            float vals[4] = {ax, ay, az, aw};
            size_t o = ((size_t)b * F66 + n) * Kp + fl;
#pragma unroll
            for (int j = 0; j < 4; j++) {
                float v = (fl + j < fw) ? vals[j] : 0.f;
                __nv_bfloat16 hh, ll; split_bf16(v, hh, ll);
                oh[o + j] = hh; ol[o + j] = ll;
            }
        }
    }
}

// ---------------- final iDCT ----------------
__global__ void final_idct(float* __restrict__ out) {
    size_t total = (size_t)BSZ * VL * F66;
    for (size_t i = (size_t)blockIdx.x * blockDim.x + threadIdx.x; i < total;
         i += (size_t)gridDim.x * blockDim.x) {
        int f = (int)(i % F66);
        int v = (int)((i / F66) % VL);
        int b = (int)(i / ((size_t)F66 * VL));
        float a = 0.f;
#pragma unroll
        for (int k = 0; k < DCTN; k++)
            a += g_dct[k * VL + v] * g_dctout[((size_t)b * F66 + f) * GCNIN + k];
        out[i] = a;
    }
}

// ---------------- host launcher ----------------
template <typename T>
static T* sym(const void* s) {
    void* p = nullptr;
    cudaGetSymbolAddress(&p, s);
    return (T*)p;
}

extern "C" void kernel_launch(void* const* d_in, const int* in_sizes, int n_in,
                              void* d_out, int out_size) {
    const float* src     = (const float*)d_in[0];
    const float* Wq1     = (const float*)d_in[1];
    const float* Wq2     = (const float*)d_in[2];
    const float* Wk1     = (const float*)d_in[3];
    const float* Wk2     = (const float*)d_in[4];
    const float* gc1_W   = (const float*)d_in[5];
    const float* gc1_att = (const float*)d_in[6];
    const float* gc1_b   = (const float*)d_in[7];
    const float* bn1_g   = (const float*)d_in[8];
    const float* bn1_b   = (const float*)d_in[9];
    const float* gcb_W   = (const float*)d_in[10];
    const float* gcb_att = (const float*)d_in[11];
    const float* gcb_b   = (const float*)d_in[12];
    const float* gcb_bn_g= (const float*)d_in[13];
    const float* gcb_bn_b= (const float*)d_in[14];
    const float* gc7_W   = (const float*)d_in[15];
    const float* gc7_att = (const float*)d_in[16];
    const float* gc7_b   = (const float*)d_in[17];
    float* out = (float*)d_out;

    cudaFuncSetAttribute(hgemm, cudaFuncAttributeMaxDynamicSharedMemorySize, HG_SMEM);
    cudaFuncSetAttribute(amix_mma, cudaFuncAttributeMaxDynamicSharedMemorySize, AM_SMEM);

    __nv_bfloat16* Xk1h = sym<__nv_bfloat16>(g_Xk1h); __nv_bfloat16* Xk1l = sym<__nv_bfloat16>(g_Xk1l);
    __nv_bfloat16* Xk2h = sym<__nv_bfloat16>(g_Xk2h); __nv_bfloat16* Xk2l = sym<__nv_bfloat16>(g_Xk2l);
    __nv_bfloat16* Xq1h = sym<__nv_bfloat16>(g_Xq1h); __nv_bfloat16* Xq1l = sym<__nv_bfloat16>(g_Xq1l);
    __nv_bfloat16* Xq2h = sym<__nv_bfloat16>(g_Xq2h); __nv_bfloat16* Xq2l = sym<__nv_bfloat16>(g_Xq2l);
    __nv_bfloat16* Wk1h = sym<__nv_bfloat16>(g_Wk1h); __nv_bfloat16* Wk1l = sym<__nv_bfloat16>(g_Wk1l);
    __nv_bfloat16* Wk2h = sym<__nv_bfloat16>(g_Wk2h); __nv_bfloat16* Wk2l = sym<__nv_bfloat16>(g_Wk2l);
    __nv_bfloat16* Wq1h = sym<__nv_bfloat16>(g_Wq1h); __nv_bfloat16* Wq1l = sym<__nv_bfloat16>(g_Wq1l);
    __nv_bfloat16* Wq2h = sym<__nv_bfloat16>(g_Wq2h); __nv_bfloat16* Wq2l = sym<__nv_bfloat16>(g_Wq2l);
    __nv_bfloat16* Wg1h = sym<__nv_bfloat16>(g_Wg1h); __nv_bfloat16* Wg1l = sym<__nv_bfloat16>(g_Wg1l);
    __nv_bfloat16* Wgbh = sym<__nv_bfloat16>(g_Wgbh); __nv_bfloat16* Wgbl = sym<__nv_bfloat16>(g_Wgbl);
    __nv_bfloat16* Th   = sym<__nv_bfloat16>(g_Th);   __nv_bfloat16* Tl   = sym<__nv_bfloat16>(g_Tl);
    __nv_bfloat16* yh   = sym<__nv_bfloat16>(g_yh);   __nv_bfloat16* yl   = sym<__nv_bfloat16>(g_yl);
    __nv_bfloat16* zh   = sym<__nv_bfloat16>(g_zh);   __nv_bfloat16* zl   = sym<__nv_bfloat16>(g_zl);
    __nv_bfloat16* Aph  = sym<__nv_bfloat16>(g_Aph);  __nv_bfloat16* Apl  = sym<__nv_bfloat16>(g_Apl);

    float* key1 = sym<float>(g_key1);
    float* key2 = sym<float>(g_key2);
    float* q1   = sym<float>(g_q1);
    float* qv   = sym<float>(g_q);
    float* patt = sym<float>(g_att);
    float* px   = sym<float>(g_x);
    float* py   = sym<float>(g_y);
    float* pz   = sym<float>(g_z);
    float* pt   = sym<float>(g_t);
    float* pdo  = sym<float>(g_dctout);

    Epi ep_relu = {nullptr, nullptr, nullptr, nullptr, 1};

    dct_build<<<1, 256>>>();

    // ---- weight preps ----
    prep_NK<<<256, 256>>>(Wk1, Wk1h, Wk1l, 512, 396, K1P);
    prep_NK<<<512, 256>>>(Wk2, Wk2h, Wk2l, 512, K2, K2);
    prep_NK<<<256, 256>>>(Wq1, Wq1h, Wq1l, 512, 396, K1P);
    prep_NK<<<512, 256>>>(Wq2, Wq2h, Wq2l, 512, K2, K2);
    prep_KN<<<64, 256>>>(gc1_W, Wg1h, Wg1l, GCNIN, 512, 64);
    for (int li = 0; li < 4; li++)
        prep_KN<<<256, 256>>>(gcb_W + (size_t)li * 512 * 512,
                              Wgbh + (size_t)li * 512 * 512,
                              Wgbl + (size_t)li * 512 * 512, 512, 512, 512);
    prep_att<<<64, 256>>>(gcb_att, gc7_att);

    // ---- key conv stack ----
    im2col_c1b<<<2048, 256>>>(src, Xk1h, Xk1l, 20, 0);
    hgemm<<<dim3(2, 80), 512, HG_SMEM>>>(Xk1h, Xk1l, Wk1h, Wk1l, key1, nullptr, nullptr, 10240, K1P, ep_relu);
    im2col_c2b<<<4096, 256>>>(key1, Xk2h, Xk2l, 16, 20);
    hgemm<<<dim3(2, 64), 512, HG_SMEM>>>(Xk2h, Xk2l, Wk2h, Wk2l, key2, nullptr, nullptr, 8192, K2, ep_relu);

    // ---- query conv stack ----
    im2col_c1b<<<1024, 256>>>(src, Xq1h, Xq1l, 5, TIN - KS_);
    hgemm<<<dim3(2, 20), 512, HG_SMEM>>>(Xq1h, Xq1l, Wq1h, Wq1l, q1, nullptr, nullptr, 2560, K1P, ep_relu);
    im2col_c2b<<<1024, 256>>>(q1, Xq2h, Xq2l, 1, 5);
    hgemm<<<dim3(2, 4), 512, HG_SMEM>>>(Xq2h, Xq2l, Wq2h, Wq2l, qv, nullptr, nullptr, 512, K2, ep_relu);

    // ---- attention + x ----
    score_att_kernel<<<BSZ, 256>>>(qv, key2, patt);
    x_build<<<BSZ, 256>>>(src);

    const int M = MROWS;

    // ---- gc1 ----
    {
        amix2<<<BSZ, 256>>>(gc1_att, px, Th, Tl, GCNIN, 64);
        Epi e = {gc1_b, bn1_g, bn1_b, nullptr, 2};
        hgemm<<<dim3(2, M / 128), 512, HG_SMEM>>>(Th, Tl, Wg1h, Wg1l, py, yh, yl, M, 64, e);
    }

    // ---- 2 stages x 2 layers ----
    for (int st = 0; st < 2; st++) {
        for (int l = 0; l < 2; l++) {
            int li = st * 2 + l;
            const __nv_bfloat16* ih = (l == 0) ? yh : zh;
            const __nv_bfloat16* il = (l == 0) ? yl : zl;
            float* o = (l == 0) ? pz : py;
            __nv_bfloat16* oh = (l == 0) ? zh : yh;
            __nv_bfloat16* ol = (l == 0) ? zl : yl;
            amix_mma<<<dim3(4, BSZ), 256, AM_SMEM>>>(Aph + li * 6400, Apl + li * 6400,
                                                     ih, il, Th, Tl, nullptr);
            Epi e = {gcb_b + (size_t)li * 512,
                     gcb_bn_g + (size_t)li * F66 * 512,
                     gcb_bn_b + (size_t)li * F66 * 512,
                     (l == 1) ? py : nullptr,
                     (l == 1) ? 3 : 2};
            hgemm<<<dim3(2, M / 128), 512, HG_SMEM>>>(Th, Tl,
                Wgbh + (size_t)li * 512 * 512, Wgbl + (size_t)li * 512 * 512,
                o, oh, ol, M, 512, e);
        }
    }

    // ---- gc7 (+x residual) ----
    {
        amix_mma<<<dim3(4, BSZ), 256, AM_SMEM>>>(Aph + 4 * 6400, Apl + 4 * 6400,
                                                 yh, yl, nullptr, nullptr, pt);
        gemm_ffma<<<dim3(1, M / BM), 256>>>(pt, gc7_W, pdo, M, GCNIN, 512, gc7_b, px);
    }

    // ---- final iDCT ----
    final_idct<<<4620, 256>>>(out);
    (void)in_sizes; (void)n_in; (void)out_size;
}